// round 15
// baseline (speedup 1.0000x reference)
#include <cuda_runtime.h>

// ExpandEvecs: out[b,k,n,m] = sum_{j<=k} ev[b,n,j] * ev[b,m,j]
// ev: [4,1,1024,16] fp32 ; out: [4,16,1024,1024] fp32 (256 MB)
// R15 = Pareto merge of the two best measurements:
//  - R1 structure: k-inner running cumsum, TILE_N=16, B-rows register-
//    resident, grid 256 (one full wave, occ 2) -> best kernel dur (44.4us)
//  - __stwt write-through stores (R14) -> wall == kernel, no dirty-L2
//    drain bubble between graph replays.

#define NDIM 1024
#define KDIM 16
#define TILE_N 16

__global__ __launch_bounds__(256, 2)
void expand_evecs_kernel(const float* __restrict__ ev, float* __restrict__ out) {
    const int b   = blockIdx.y;
    const int n0  = blockIdx.x * TILE_N;
    const int tid = threadIdx.x;
    const int m   = tid << 2;           // 4 consecutive m-columns per thread

    __shared__ float a_s[TILE_N][KDIM]; // 16 x 16 A-rows for this n-tile

    const float* evb = ev + (size_t)b * NDIM * KDIM;

    // Load A tile: 256 contiguous floats, one per thread.
    a_s[tid >> 4][tid & 15] = evb[(size_t)n0 * KDIM + tid];

    // Load this thread's 4 B-rows (m..m+3), register-resident.
    float bw[4][KDIM];
    const float4* evb4 = (const float4*)evb;
    #pragma unroll
    for (int i = 0; i < 4; ++i) {
        #pragma unroll
        for (int q = 0; q < 4; ++q)
            ((float4*)bw[i])[q] = evb4[(size_t)(m + i) * (KDIM / 4) + q];
    }
    __syncthreads();

    float* ob = out + (size_t)b * KDIM * NDIM * NDIM;
    const size_t plane = (size_t)NDIM * NDIM;

    for (int nn = 0; nn < TILE_N; ++nn) {
        float4 acc = make_float4(0.f, 0.f, 0.f, 0.f);
        float* orow = ob + (size_t)(n0 + nn) * NDIM + m;
        #pragma unroll
        for (int k = 0; k < KDIM; ++k) {
            const float ak = a_s[nn][k];
            acc.x = fmaf(ak, bw[0][k], acc.x);
            acc.y = fmaf(ak, bw[1][k], acc.y);
            acc.z = fmaf(ak, bw[2][k], acc.z);
            acc.w = fmaf(ak, bw[3][k], acc.w);
            __stwt((float4*)(orow + (size_t)k * plane), acc);   // write-through
        }
    }
}

extern "C" void kernel_launch(void* const* d_in, const int* in_sizes, int n_in,
                              void* d_out, int out_size) {
    const float* ev = (const float*)d_in[0];
    float* out = (float*)d_out;
    const int B = in_sizes[0] / (NDIM * KDIM);   // = 4
    dim3 grid(NDIM / TILE_N, B);                 // 64 x 4 = 256 blocks, one wave
    expand_evecs_kernel<<<grid, 256>>>(ev, out);
}